// round 15
// baseline (speedup 1.0000x reference)
#include <cuda_runtime.h>
#include <math.h>

#define MAXN 2048
__device__ float    g_x2[MAXN];   // ||x_j||^2
__device__ float    g_r[MAXN];    // x_tan_j . w_r
__device__ unsigned g_ctr;        // barrier ticket counter (monotonic across replays)

__device__ __forceinline__ float warp_sum(float v) {
#pragma unroll
    for (int o = 16; o; o >>= 1) v += __shfl_xor_sync(0xffffffffu, v, o);
    return v;
}

__device__ __forceinline__ float dot8(float4 a, float4 b, float4 c, float4 d) {
    return fmaf(a.x, c.x, fmaf(a.y, c.y, fmaf(a.z, c.z, fmaf(a.w, c.w,
           fmaf(b.x, d.x, fmaf(b.y, d.y, fmaf(b.z, d.z, b.w * d.w)))))));
}

__device__ __forceinline__ float fast_atanh(float v) {
    return 0.5f * __logf(__fdividef(1.f + v, 1.f - v));
}

#define LCAP 40   // per-half-row neighbor cap (expected ~8)

// Single kernel: 256 threads (8 warps), 4 rows per block, 2 warps per row.
// Phase 0: warps 0-3 compute per-row scalars into global scratch (+smem);
//          adj loads + compaction overlap this and the grid barrier.
// Grid barrier: ticket-based, replay-safe (no reset needed); entire grid
//   (384 blocks <= 148 SMs * 4 blocks) is resident in wave 1, so safe.
// Phase 1: slim software-pipelined pair rounds (D-only reduction), epilogue.
__global__ __launch_bounds__(256, 4)
void fused_kernel(const float* __restrict__ x,
                  const float* __restrict__ adj,
                  const float* __restrict__ att_w,
                  const float* __restrict__ att_b,
                  float* __restrict__ out, int N) {
    __shared__ float s_part[8][64];
    __shared__ float s_S1[8];
    __shared__ float s_rx2[4];
    __shared__ float s_rli[4];
    __shared__ int   s_list[8][LCAP];

    int tid   = threadIdx.x;
    int w     = tid >> 5;
    int lane  = tid & 31;
    int rloc  = w >> 1;
    int half  = w & 1;
    int row   = blockIdx.x * 4 + rloc;
    int p     = lane >> 3;              // pair-slot group 0..3
    int q     = lane & 7;               // lane in group

    // ---- adj loads first (deepest latency; 6 in flight per lane) ----
    const float4* arow = (const float4*)(adj + (size_t)row * N);
    int nq = N >> 2;
    int qh = nq >> 1;
    int qb = half * qh;
    float4 v[6];
#pragma unroll
    for (int c = 0; c < 6; c++) {
        int ci = c * 32 + lane;
        v[c] = (ci < qh) ? __ldg(&arow[qb + ci])
                         : make_float4(0.f, 0.f, 0.f, 0.f);
    }

    // ---- x_i slice for the pair loop ----
    const float4* xrow = (const float4*)(x + row * 64);
    float4 xa = __ldg(&xrow[q]);
    float4 xb = __ldg(&xrow[8 + q]);
    float bias = __ldg(att_b);

    // ---- phase 0: warps 0-3 compute scalars for local rows 0-3 ----
    if (w < 4) {
        int prow = blockIdx.x * 4 + w;
        float x0 = x[prow * 64 + lane];
        float x1 = x[prow * 64 + 32 + lane];
        float n2 = warp_sum(x0 * x0 + x1 * x1);
        float dl = warp_sum(x0 * att_w[lane]      + x1 * att_w[32 + lane]);
        float dr = warp_sum(x0 * att_w[64 + lane] + x1 * att_w[96 + lane]);
        if (lane == 0) {
            float pn  = sqrtf(n2);
            float pnc = fmaxf(pn, 1e-15f);
            float s   = __fdividef(fast_atanh(fminf(pnc, 1.f - 1e-7f)), pnc);
            g_x2[prow] = n2;
            g_r[prow]  = s * dr;
            s_rx2[w]   = n2;
            s_rli[w]   = s * dl;
        }
    }

    // ---- compaction (independent of scalars): 24-bit mask + warp scan ----
    unsigned m24 = 0;
#pragma unroll
    for (int c = 0; c < 6; c++) {
        if (v[c].x != 0.f) m24 |= 1u << (c * 4 + 0);
        if (v[c].y != 0.f) m24 |= 1u << (c * 4 + 1);
        if (v[c].z != 0.f) m24 |= 1u << (c * 4 + 2);
        if (v[c].w != 0.f) m24 |= 1u << (c * 4 + 3);
    }
    int cnt = __popc(m24);
    int pre = cnt;
#pragma unroll
    for (int o = 1; o <= 16; o <<= 1) {
        int t = __shfl_up_sync(0xffffffffu, pre, o);
        if (lane >= o) pre += t;
    }
    int total = __shfl_sync(0xffffffffu, pre, 31);
    pre -= cnt;
    unsigned mm = m24;
    int base = pre;
    while (mm) {
        int b = __ffs(mm) - 1; mm &= mm - 1;
        if (base < LCAP)
            s_list[w][base] = (qb + (b >> 2) * 32 + lane) * 4 + (b & 3);
        base++;
    }
    int nwr = min(total, LCAP);

    // ---- grid barrier (replay-safe ticket scheme) ----
    __syncthreads();                    // own-block scalar writes complete
    if (tid == 0) {
        __threadfence();                // release g_x2/g_r
        unsigned grid   = gridDim.x;
        unsigned ticket = atomicAdd(&g_ctr, 1u);
        unsigned target = (ticket / grid + 1u) * grid;
        volatile unsigned* vc = &g_ctr;
        while (*vc < target) { __nanosleep(64); }
        __threadfence();                // acquire all blocks' writes
    }
    __syncthreads();

    float x2   = s_rx2[rloc];
    float li   = s_rli[rloc];
    float beta = 1.f - x2;

    // ---- software-pipelined pair rounds (D-only reduction) ----
    float acc[8];
#pragma unroll
    for (int k = 0; k < 8; k++) acc[k] = 0.f;
    float ga = 0.f;

    int rounds = (nwr + 3) >> 2;        // warp-uniform
    int   s0 = p;
    bool  a0 = (s0 < nwr);
    int   j0 = a0 ? s_list[w][s0] : row;
    const float4* xj0 = (const float4*)(x + j0 * 64);
    float4 ya = __ldg(&xj0[q]);
    float4 yb = __ldg(&xj0[8 + q]);
    float y2c = __ldg(&g_x2[j0]);
    float rjc = __ldg(&g_r[j0]);

    for (int r = 0; r < rounds; r++) {
        int   s1 = s0 + 4;
        bool  a1 = (s1 < nwr);
        int   j1 = a1 ? s_list[w][s1] : row;
        const float4* xj1 = (const float4*)(x + j1 * 64);
        float4 za = __ldg(&xj1[q]);
        float4 zb = __ldg(&xj1[8 + q]);
        float y2n = __ldg(&g_x2[j1]);
        float rjn = __ldg(&g_r[j1]);

        float D = dot8(ya, yb, xa, xb);
#pragma unroll
        for (int o = 1; o <= 4; o <<= 1)
            D += __shfl_xor_sync(0xffffffffu, D, o);

        float y2 = y2c, rv = rjc;
        float alpha = 1.f - 2.f * D + y2;
        float den   = fmaxf(1.f - 2.f * D + x2 * y2, 1e-15f);
        float nn    = alpha * alpha * x2 - 2.f * alpha * beta * D
                    + beta * beta * y2;
        float sn    = fmaxf(__fdividef(sqrtf(fmaxf(nn, 0.f)), den), 1e-15f);
        float ratio = __fdividef(fast_atanh(fminf(sn, 1.f - 1e-7f)), sn);
        float sig   = __fdividef(1.f, 1.f + __expf(-(li + rv + bias)));
        float g     = a0 ? __fdividef(sig * beta * ratio, den) : 0.f;

        acc[0] = fmaf(g, ya.x, acc[0]);
        acc[1] = fmaf(g, ya.y, acc[1]);
        acc[2] = fmaf(g, ya.z, acc[2]);
        acc[3] = fmaf(g, ya.w, acc[3]);
        acc[4] = fmaf(g, yb.x, acc[4]);
        acc[5] = fmaf(g, yb.y, acc[5]);
        acc[6] = fmaf(g, yb.z, acc[6]);
        acc[7] = fmaf(g, yb.w, acc[7]);
        ga += (q == 0) ? g * alpha : 0.f;

        ya = za; yb = zb; y2c = y2n; rjc = rjn; a0 = a1; s0 = s1;
    }

    // cross-group reduce (4 pair-groups -> group 0's dim slices)
#pragma unroll
    for (int k = 0; k < 8; k++) {
        acc[k] += __shfl_xor_sync(0xffffffffu, acc[k], 8);
        acc[k] += __shfl_xor_sync(0xffffffffu, acc[k], 16);
    }
    if (p == 0) {
        *(float4*)&s_part[w][q * 4]      = make_float4(acc[0], acc[1], acc[2], acc[3]);
        *(float4*)&s_part[w][32 + q * 4] = make_float4(acc[4], acc[5], acc[6], acc[7]);
    }
    ga += __shfl_xor_sync(0xffffffffu, ga, 8);
    ga += __shfl_xor_sync(0xffffffffu, ga, 16);
    if (lane == 0) s_S1[w] = ga;

    __syncthreads();

    // ---- epilogue: warp k (k<4) finalizes local row k ----
    if (w < 4) {
        int orow = blockIdx.x * 4 + w;
        float ex2   = s_rx2[w];
        float ebeta = 1.f - ex2;
        float S1 = s_S1[2 * w] + s_S1[2 * w + 1];
        float sum0 = s_part[2 * w][lane]      + s_part[2 * w + 1][lane];
        float sum1 = s_part[2 * w][lane + 32] + s_part[2 * w + 1][lane + 32];
        float xi0 = __ldg(&x[orow * 64 + lane]);
        float xi1 = __ldg(&x[orow * 64 + 32 + lane]);
        float u0 = fmaf(ebeta, sum0, -S1 * xi0);
        float u1 = fmaf(ebeta, sum1, -S1 * xi1);

        float un2 = warp_sum(u0 * u0 + u1 * u1);
        float du  = warp_sum(xi0 * u0 + xi1 * u1);
        float un  = fmaxf(sqrtf(un2), 1e-15f);
        float lam = fmaxf(2.f / ebeta, 1e-15f);
        float t   = tanhf(0.5f * lam * un);
        float sc  = t / un;
        float v0 = sc * u0, v1 = sc * u1;
        float y2s = sc * sc * un2;
        float xys = sc * du;
        float ca   = 1.f + 2.f * xys + y2s;
        float den2 = fmaxf(1.f + 2.f * xys + ex2 * y2s, 1e-15f);
        float o0 = (ca * xi0 + ebeta * v0) / den2;
        float o1 = (ca * xi1 + ebeta * v1) / den2;
        float on = fmaxf(sqrtf(warp_sum(o0 * o0 + o1 * o1)), 1e-15f);
        float maxn  = 1.f - 0.004f;
        float scale = (on > maxn) ? (maxn / on) : 1.f;
        out[orow * 64 + lane]      = o0 * scale;
        out[orow * 64 + 32 + lane] = o1 * scale;
    }
}

extern "C" void kernel_launch(void* const* d_in, const int* in_sizes, int n_in,
                              void* d_out, int out_size) {
    const float* x     = (const float*)d_in[0];
    const float* adj   = (const float*)d_in[1];
    const float* att_w = (const float*)d_in[2];
    const float* att_b = (const float*)d_in[3];
    int d = in_sizes[2] / 2;          // 64
    int N = in_sizes[0] / d;          // 1536
    fused_kernel<<<N / 4, 256>>>(x, adj, att_w, att_b, (float*)d_out, N);
}

// round 16
// speedup vs baseline: 1.1361x; 1.1361x over previous
#include <cuda_runtime.h>
#include <math.h>

#define MAXN 2048
__device__ float g_x2[MAXN];   // ||x_j||^2
__device__ float g_r[MAXN];    // x_tan_j . w_r

__device__ __forceinline__ float warp_sum(float v) {
#pragma unroll
    for (int o = 16; o; o >>= 1) v += __shfl_xor_sync(0xffffffffu, v, o);
    return v;
}

__device__ __forceinline__ float dot8(float4 a, float4 b, float4 c, float4 d) {
    return fmaf(a.x, c.x, fmaf(a.y, c.y, fmaf(a.z, c.z, fmaf(a.w, c.w,
           fmaf(b.x, d.x, fmaf(b.y, d.y, fmaf(b.z, d.z, b.w * d.w)))))));
}

__device__ __forceinline__ float fast_atanh(float v) {
    return 0.5f * __logf(__fdividef(1.f + v, 1.f - v));
}

// K1: warp per row — per-row scalars computed ONCE.
__global__ __launch_bounds__(256, 8)
void pre_kernel(const float* __restrict__ x,
                const float* __restrict__ att_w, int N) {
    int row  = blockIdx.x * 8 + (threadIdx.x >> 5);
    int lane = threadIdx.x & 31;
    if (row >= N) return;
    float x0 = x[row * 64 + lane];
    float x1 = x[row * 64 + 32 + lane];
    float n2 = warp_sum(x0 * x0 + x1 * x1);
    float dl = warp_sum(x0 * att_w[lane]      + x1 * att_w[32 + lane]);
    float dr = warp_sum(x0 * att_w[64 + lane] + x1 * att_w[96 + lane]);
    if (lane == 0) {
        float pn  = sqrtf(n2);
        float pnc = fmaxf(pn, 1e-15f);
        float s   = __fdividef(fast_atanh(fminf(pnc, 1.f - 1e-7f)), pnc);
        g_x2[row] = n2;
        g_l_unused:;
        g_r[row]  = s * dr;
        // l_i is recomputed cheaply in K2 via dl path? No: store in g_x2-style array:
    }
    // store l_i too (separate array kept below)
}

__device__ float g_l[MAXN];    // x_tan_i . w_l

__global__ __launch_bounds__(256, 8)
void pre_kernel_l(const float* __restrict__ x,
                  const float* __restrict__ att_w, int N) {
    // merged into pre_kernel in practice; kept separate symbol unused
}

#define LCAP 40   // per-half-row neighbor cap (expected ~8)

// K2: 256 threads (8 warps), 4 rows per block, 2 warps per row.
// Launched with PDL; prologue (adj loads + compaction) overlaps K1, then
// cudaGridDependencySynchronize() gates the first use of g_x2/g_r/g_l.
__global__ __launch_bounds__(256, 4)
void fused_kernel(const float* __restrict__ x,
                  const float* __restrict__ adj,
                  const float* __restrict__ att_b,
                  float* __restrict__ out, int N) {
    __shared__ float s_part[8][64];
    __shared__ float s_S1[8];
    __shared__ int   s_list[8][LCAP];

    int tid   = threadIdx.x;
    int w     = tid >> 5;
    int lane  = tid & 31;
    int rloc  = w >> 1;
    int half  = w & 1;
    int row   = blockIdx.x * 4 + rloc;
    int p     = lane >> 3;              // pair-slot group 0..3
    int q     = lane & 7;               // lane in group

    // ---- adj loads first (deepest latency; overlaps K1 under PDL) ----
    const float4* arow = (const float4*)(adj + (size_t)row * N);
    int nq = N >> 2;
    int qh = nq >> 1;
    int qb = half * qh;
    float4 v[6];
#pragma unroll
    for (int c = 0; c < 6; c++) {
        int ci = c * 32 + lane;
        v[c] = (ci < qh) ? __ldg(&arow[qb + ci])
                         : make_float4(0.f, 0.f, 0.f, 0.f);
    }

    // ---- x_i slice ----
    const float4* xrow = (const float4*)(x + row * 64);
    float4 xa = __ldg(&xrow[q]);
    float4 xb = __ldg(&xrow[8 + q]);
    float bias = __ldg(att_b);

    // ---- compaction: per-lane 24-bit mask + ONE warp prefix scan ----
    unsigned m24 = 0;
#pragma unroll
    for (int c = 0; c < 6; c++) {
        if (v[c].x != 0.f) m24 |= 1u << (c * 4 + 0);
        if (v[c].y != 0.f) m24 |= 1u << (c * 4 + 1);
        if (v[c].z != 0.f) m24 |= 1u << (c * 4 + 2);
        if (v[c].w != 0.f) m24 |= 1u << (c * 4 + 3);
    }
    int cnt = __popc(m24);
    int pre = cnt;
#pragma unroll
    for (int o = 1; o <= 16; o <<= 1) {
        int t = __shfl_up_sync(0xffffffffu, pre, o);
        if (lane >= o) pre += t;
    }
    int total = __shfl_sync(0xffffffffu, pre, 31);
    pre -= cnt;
    unsigned mm = m24;
    int base = pre;
    while (mm) {
        int b = __ffs(mm) - 1; mm &= mm - 1;
        if (base < LCAP)
            s_list[w][base] = (qb + (b >> 2) * 32 + lane) * 4 + (b & 3);
        base++;
    }
    int nwr = min(total, LCAP);
    __syncwarp();

    // ---- PDL gate: wait for pre_kernel's g_x2/g_r/g_l before first use ----
#if __CUDA_ARCH__ >= 900
    cudaGridDependencySynchronize();
#endif

    float x2   = __ldg(&g_x2[row]);
    float li   = __ldg(&g_l[row]);
    float beta = 1.f - x2;

    // ---- software-pipelined pair rounds (D-only reduction) ----
    float acc[8];
#pragma unroll
    for (int k = 0; k < 8; k++) acc[k] = 0.f;
    float ga = 0.f;

    int rounds = (nwr + 3) >> 2;        // warp-uniform
    int   s0 = p;
    bool  a0 = (s0 < nwr);
    int   j0 = a0 ? s_list[w][s0] : row;
    const float4* xj0 = (const float4*)(x + j0 * 64);
    float4 ya = __ldg(&xj0[q]);
    float4 yb = __ldg(&xj0[8 + q]);
    float y2c = __ldg(&g_x2[j0]);
    float rjc = __ldg(&g_r[j0]);

    for (int r = 0; r < rounds; r++) {
        int   s1 = s0 + 4;
        bool  a1 = (s1 < nwr);
        int   j1 = a1 ? s_list[w][s1] : row;
        const float4* xj1 = (const float4*)(x + j1 * 64);
        float4 za = __ldg(&xj1[q]);
        float4 zb = __ldg(&xj1[8 + q]);
        float y2n = __ldg(&g_x2[j1]);
        float rjn = __ldg(&g_r[j1]);

        float D = dot8(ya, yb, xa, xb);
#pragma unroll
        for (int o = 1; o <= 4; o <<= 1)
            D += __shfl_xor_sync(0xffffffffu, D, o);

        float y2 = y2c, rv = rjc;
        float alpha = 1.f - 2.f * D + y2;
        float den   = fmaxf(1.f - 2.f * D + x2 * y2, 1e-15f);
        float nn    = alpha * alpha * x2 - 2.f * alpha * beta * D
                    + beta * beta * y2;
        float sn    = fmaxf(__fdividef(sqrtf(fmaxf(nn, 0.f)), den), 1e-15f);
        float ratio = __fdividef(fast_atanh(fminf(sn, 1.f - 1e-7f)), sn);
        float sig   = __fdividef(1.f, 1.f + __expf(-(li + rv + bias)));
        float g     = a0 ? __fdividef(sig * beta * ratio, den) : 0.f;

        acc[0] = fmaf(g, ya.x, acc[0]);
        acc[1] = fmaf(g, ya.y, acc[1]);
        acc[2] = fmaf(g, ya.z, acc[2]);
        acc[3] = fmaf(g, ya.w, acc[3]);
        acc[4] = fmaf(g, yb.x, acc[4]);
        acc[5] = fmaf(g, yb.y, acc[5]);
        acc[6] = fmaf(g, yb.z, acc[6]);
        acc[7] = fmaf(g, yb.w, acc[7]);
        ga += (q == 0) ? g * alpha : 0.f;

        ya = za; yb = zb; y2c = y2n; rjc = rjn; a0 = a1; s0 = s1;
    }

    // cross-group reduce (4 pair-groups -> group 0's dim slices)
#pragma unroll
    for (int k = 0; k < 8; k++) {
        acc[k] += __shfl_xor_sync(0xffffffffu, acc[k], 8);
        acc[k] += __shfl_xor_sync(0xffffffffu, acc[k], 16);
    }
    if (p == 0) {
        *(float4*)&s_part[w][q * 4]      = make_float4(acc[0], acc[1], acc[2], acc[3]);
        *(float4*)&s_part[w][32 + q * 4] = make_float4(acc[4], acc[5], acc[6], acc[7]);
    }
    ga += __shfl_xor_sync(0xffffffffu, ga, 8);
    ga += __shfl_xor_sync(0xffffffffu, ga, 16);
    if (lane == 0) s_S1[w] = ga;

    __syncthreads();                    // the ONLY block-wide sync

    // ---- epilogue: warp k (k<4) finalizes local row k ----
    if (w < 4) {
        int orow = blockIdx.x * 4 + w;
        float ex2   = __ldg(&g_x2[orow]);
        float ebeta = 1.f - ex2;
        float S1 = s_S1[2 * w] + s_S1[2 * w + 1];
        float sum0 = s_part[2 * w][lane]      + s_part[2 * w + 1][lane];
        float sum1 = s_part[2 * w][lane + 32] + s_part[2 * w + 1][lane + 32];
        float xi0 = __ldg(&x[orow * 64 + lane]);
        float xi1 = __ldg(&x[orow * 64 + 32 + lane]);
        float u0 = fmaf(ebeta, sum0, -S1 * xi0);
        float u1 = fmaf(ebeta, sum1, -S1 * xi1);

        float un2 = warp_sum(u0 * u0 + u1 * u1);
        float du  = warp_sum(xi0 * u0 + xi1 * u1);
        float un  = fmaxf(sqrtf(un2), 1e-15f);
        float lam = fmaxf(2.f / ebeta, 1e-15f);
        float t   = tanhf(0.5f * lam * un);
        float sc  = t / un;
        float v0 = sc * u0, v1 = sc * u1;
        float y2s = sc * sc * un2;
        float xys = sc * du;
        float ca   = 1.f + 2.f * xys + y2s;
        float den2 = fmaxf(1.f + 2.f * xys + ex2 * y2s, 1e-15f);
        float o0 = (ca * xi0 + ebeta * v0) / den2;
        float o1 = (ca * xi1 + ebeta * v1) / den2;
        float on = fmaxf(sqrtf(warp_sum(o0 * o0 + o1 * o1)), 1e-15f);
        float maxn  = 1.f - 0.004f;
        float scale = (on > maxn) ? (maxn / on) : 1.f;
        out[orow * 64 + lane]      = o0 * scale;
        out[orow * 64 + 32 + lane] = o1 * scale;
    }
}

// Full pre-kernel (computes all three scalars; supersedes the stub above)
__global__ __launch_bounds__(256, 8)
void pre_kernel_full(const float* __restrict__ x,
                     const float* __restrict__ att_w, int N) {
    int row  = blockIdx.x * 8 + (threadIdx.x >> 5);
    int lane = threadIdx.x & 31;
    if (row >= N) return;
    float x0 = x[row * 64 + lane];
    float x1 = x[row * 64 + 32 + lane];
    float n2 = warp_sum(x0 * x0 + x1 * x1);
    float dl = warp_sum(x0 * att_w[lane]      + x1 * att_w[32 + lane]);
    float dr = warp_sum(x0 * att_w[64 + lane] + x1 * att_w[96 + lane]);
    if (lane == 0) {
        float pn  = sqrtf(n2);
        float pnc = fmaxf(pn, 1e-15f);
        float s   = __fdividef(fast_atanh(fminf(pnc, 1.f - 1e-7f)), pnc);
        g_x2[row] = n2;
        g_l[row]  = s * dl;
        g_r[row]  = s * dr;
    }
}

extern "C" void kernel_launch(void* const* d_in, const int* in_sizes, int n_in,
                              void* d_out, int out_size) {
    const float* x     = (const float*)d_in[0];
    const float* adj   = (const float*)d_in[1];
    const float* att_w = (const float*)d_in[2];
    const float* att_b = (const float*)d_in[3];
    float* outp        = (float*)d_out;
    int d = in_sizes[2] / 2;          // 64
    int N = in_sizes[0] / d;          // 1536

    pre_kernel_full<<<(N + 7) / 8, 256>>>(x, att_w, N);

    cudaLaunchConfig_t cfg = {};
    cfg.gridDim  = dim3(N / 4, 1, 1);
    cfg.blockDim = dim3(256, 1, 1);
    cfg.dynamicSmemBytes = 0;
    cfg.stream = 0;
    cudaLaunchAttribute at[1];
    at[0].id = cudaLaunchAttributeProgrammaticStreamSerialization;
    at[0].val.programmaticStreamSerializationAllowed = 1;
    cfg.attrs = at;
    cfg.numAttrs = 1;
    cudaLaunchKernelEx(&cfg, fused_kernel, x, adj, att_b, outp, N);
}